// round 15
// baseline (speedup 1.0000x reference)
#include <cuda_runtime.h>
#include <cuda_bf16.h>

// Problem constants (match reference_code)
#define NN 262144
#define KK 1024
#define DD 256
#define NBLK 128              // fused-prologue CTAs (all co-resident)
#define CHUNK 2048            // indices per CTA (NN / NBLK)
#define TILE 256              // reduce: order positions per CTA (uniform work)
#define NT (NN / TILE)        // 1024 reduce tiles
#define NPREF 480             // reduce CTAs that L2-prefetch their natural chunk
#define DECAY 0.99f
#define ONE_MINUS_DECAY 0.01f
#define EPS 1e-5f

// Scratch (device globals; no allocation allowed)
__device__ int      g_kcursor[KK];       // per-code running base (returning atomics);
                                         // after barrier = code totals. Reset by finishers.
__device__ int      g_offsets[KK + 1];   // exclusive scan over codes
__device__ int      g_order[NN];         // row ids grouped by code
__device__ int      g_tilecode[NT];      // code containing order position 256*b
__device__ int      g_expected[KK];      // #tiles overlapping code k (overwritten/launch)
__device__ int      g_done[KK];          // completion counters (reset by finishers)
__device__ float    g_sum[KK * DD];      // REDG target (zeroed by finishers/static)
__device__ float    g_inv_smoothed[KK];
__device__ unsigned g_bar_cnt[2];        // software grid barrier state
__device__ unsigned g_bar_gen[2];        // (zero-init; replay-safe: gen monotone)

// ---------------------------------------------------------------------------
// Software grid barrier (all NBLK CTAs co-resident by construction).
// ---------------------------------------------------------------------------
__device__ __forceinline__ void grid_barrier(int id) {
    __syncthreads();
    if (threadIdx.x == 0) {
        volatile unsigned* genp = &g_bar_gen[id];
        unsigned gen = *genp;
        __threadfence();
        unsigned arrived = atomicAdd(&g_bar_cnt[id], 1u);
        if (arrived == (unsigned)(NBLK - 1)) {
            g_bar_cnt[id] = 0u;
            __threadfence();
            *genp = gen + 1u;
        } else {
            while (*genp == gen) { __nanosleep(64); }
        }
        __threadfence();
    }
    __syncthreads();
}

// ---------------------------------------------------------------------------
// Fused prologue (ONE grid barrier):
//   A: per-CTA smem hist; base-in-code via returning global atomicAdd.
//   barrier: g_kcursor now holds code totals.
//   C: replicated code scan -> exclusive offsets; CTA 32 writes outputs,
//      tile->code map, expected tile counts, and (w.h.p. never) empty-code EMA.
//   D: scatter with cursor = excl + base_in_code + local rank.
// ---------------------------------------------------------------------------
__global__ void __launch_bounds__(1024) k_prologue(
    const int2* __restrict__ idx2,
    const float* __restrict__ cluster_size,
    float* __restrict__ out_cs,
    const float4* __restrict__ embed_avg,
    float4* __restrict__ out_ea,
    float4* __restrict__ out_norm) {
    __shared__ int   h[KK];          // hist, then scatter cursors
    __shared__ int   sh_wsum[32];
    __shared__ float sh_wred[32];
    __shared__ float sh_n;

    int t = threadIdx.x;
    int b = blockIdx.x;
    int lane = t & 31, warp = t >> 5;

    // ---- Phase A: per-CTA histogram (one int2 load -> registers) ----
    int base = b * CHUNK;
    int2 kk = idx2[(base >> 1) + t];     // indices base+2t, base+2t+1
    int k0 = kk.x, k1 = kk.y;
    h[t] = 0;
    __syncthreads();
    atomicAdd(&h[k0], 1);
    atomicAdd(&h[k1], 1);
    __syncthreads();
    int cnt = h[t];
    // Returning global atomic: my block's base within code t's span.
    int base_in_code = atomicAdd(&g_kcursor[t], cnt);

    // EARLY PDL trigger: reduce grid launches now and prefetches into L2.
    cudaTriggerProgrammaticLaunchCompletion();

    grid_barrier(0);    // after this, g_kcursor[t] == total count of code t

    // ---- Phase C (replicated in every CTA): scan code totals -> excl offset ----
    int c = g_kcursor[t];
    int incl = c;
    #pragma unroll
    for (int o = 1; o < 32; o <<= 1) {
        int x = __shfl_up_sync(0xffffffffu, incl, o);
        if (lane >= o) incl += x;
    }
    if (lane == 31) sh_wsum[warp] = incl;
    __syncthreads();
    if (warp == 0) {
        int s = sh_wsum[lane];
        int si = s;
        #pragma unroll
        for (int o = 1; o < 32; o <<= 1) {
            int x = __shfl_up_sync(0xffffffffu, si, o);
            if (lane >= o) si += x;
        }
        sh_wsum[lane] = si - s;
    }
    __syncthreads();
    int excl = incl - c + sh_wsum[warp];

    if (b == 32) {
        // Outputs needed downstream (one CTA writes).
        g_offsets[t] = excl;
        if (t == KK - 1) g_offsets[KK] = excl + c;

        int endp = excl + c;
        // Tile->code map + expected tile count for the finisher protocol.
        for (int m = (excl + TILE - 1) & ~(TILE - 1); m < endp; m += TILE)
            g_tilecode[m / TILE] = t;
        g_expected[t] = (c > 0) ? ((endp - 1) / TILE - excl / TILE + 1) : 0;

        float ncs = cluster_size[t] * DECAY + ONE_MINUS_DECAY * (float)c;
        out_cs[t] = ncs;

        float v = ncs;
        #pragma unroll
        for (int o = 16; o > 0; o >>= 1)
            v += __shfl_down_sync(0xffffffffu, v, o);
        if (lane == 0) sh_wred[warp] = v;
        __syncthreads();
        if (warp == 0) {
            float s = sh_wred[lane];
            #pragma unroll
            for (int o = 16; o > 0; o >>= 1)
                s += __shfl_down_sync(0xffffffffu, s, o);
            if (lane == 0) sh_n = s;
        }
        __syncthreads();
        float n = sh_n;

        float smoothed = (ncs + EPS) / (n + (float)KK * EPS) * n;
        float inv = 1.0f / smoothed;
        g_inv_smoothed[t] = inv;

        // Empty code (w.h.p. never with N>>K): no reduce finisher -> EMA here.
        if (c == 0) {
            const float4* eap = embed_avg + (size_t)t * 64;
            float4*       oea = out_ea   + (size_t)t * 64;
            float4*       onr = out_norm + (size_t)t * 64;
            for (int i = 0; i < 64; ++i) {
                float4 ea = eap[i];
                float4 nea = make_float4(ea.x * DECAY, ea.y * DECAY,
                                         ea.z * DECAY, ea.w * DECAY);
                oea[i] = nea;
                onr[i] = make_float4(nea.x * inv, nea.y * inv,
                                     nea.z * inv, nea.w * inv);
            }
        }
    }

    // ---- Phase D: scatter, cursors built locally ----
    __syncthreads();                 // everyone done reading h[t] as cnt
    h[t] = excl + base_in_code;
    __syncthreads();
    int i0 = base + 2 * t;
    int p0 = atomicAdd(&h[k0], 1);
    g_order[p0] = i0;
    int p1 = atomicAdd(&h[k1], 1);
    g_order[p1] = i0 + 1;
}

// ---------------------------------------------------------------------------
// Reduce + fused epilogue:
//  - launches early via PDL; CTAs b<NPREF L2-prefetch their natural chunk
//    during the prologue's latency-bound window.
//  - UNIFORM tiles over the order array; 8-deep float4 streams; per-segment
//    flush via float atomicAdd (REDG) into g_sum.
//  - completion counters: the CTA that finishes a code's last segment becomes
//    its FINISHER and performs the EMA+normalize for that code in-kernel,
//    then resets the code's scratch for the next graph replay.
// ---------------------------------------------------------------------------
__global__ void __launch_bounds__(128, 7) k_reduce(
    const float4* __restrict__ enc,        // [N, 64] float4
    const float4* __restrict__ embed_avg,  // [K, 64] float4
    float4* __restrict__ out_ea,
    float4* __restrict__ out_norm) {
    __shared__ int ord[TILE];
    __shared__ int fin_k;

    int b = blockIdx.x;
    int d4 = threadIdx.x & 63;      // float4 column 0..63
    int ph = threadIdx.x >> 6;      // row phase 0..1
    int s = b * TILE;

    // ---- Overlap window: L2 prefetch of this CTA's natural chunk ----
    if (b < NPREF) {
        const char* pbase = reinterpret_cast<const char*>(enc) +
                            (size_t)b * TILE * (DD * 4);
        #pragma unroll
        for (int i = 0; i < 16; ++i) {
            const char* p = pbase + ((size_t)(i * 128 + threadIdx.x) << 7);
            asm volatile("prefetch.global.L2 [%0];" :: "l"(p));
        }
    }

    // Wait for the prologue grid (PDL; full-grid completion + visibility).
    cudaGridDependencySynchronize();

    ord[threadIdx.x]       = g_order[s + threadIdx.x];
    ord[threadIdx.x + 128] = g_order[s + threadIdx.x + 128];
    __syncthreads();

    int k = g_tilecode[b];
    int a = s;
    int send = s + TILE;

    while (a < send && k < KK) {
        int e2 = g_offsets[k + 1];
        if (e2 > send) e2 = send;
        int la = a - s;
        int le = e2 - s;

        if (le > la) {
            float4 a0 = make_float4(0.f, 0.f, 0.f, 0.f);
            float4 a1 = make_float4(0.f, 0.f, 0.f, 0.f);
            float4 a2 = make_float4(0.f, 0.f, 0.f, 0.f);
            float4 a3 = make_float4(0.f, 0.f, 0.f, 0.f);
            float4 a4 = make_float4(0.f, 0.f, 0.f, 0.f);
            float4 a5 = make_float4(0.f, 0.f, 0.f, 0.f);
            float4 a6 = make_float4(0.f, 0.f, 0.f, 0.f);
            float4 a7 = make_float4(0.f, 0.f, 0.f, 0.f);

            int j = la + ph;
            for (; j + 14 < le; j += 16) {
                int r0 = ord[j];
                int r1 = ord[j + 2];
                int r2 = ord[j + 4];
                int r3 = ord[j + 6];
                int r4 = ord[j + 8];
                int r5 = ord[j + 10];
                int r6 = ord[j + 12];
                int r7 = ord[j + 14];
                float4 v0 = __ldcs(enc + (size_t)r0 * 64 + d4);
                float4 v1 = __ldcs(enc + (size_t)r1 * 64 + d4);
                float4 v2 = __ldcs(enc + (size_t)r2 * 64 + d4);
                float4 v3 = __ldcs(enc + (size_t)r3 * 64 + d4);
                float4 v4 = __ldcs(enc + (size_t)r4 * 64 + d4);
                float4 v5 = __ldcs(enc + (size_t)r5 * 64 + d4);
                float4 v6 = __ldcs(enc + (size_t)r6 * 64 + d4);
                float4 v7 = __ldcs(enc + (size_t)r7 * 64 + d4);
                a0.x += v0.x; a0.y += v0.y; a0.z += v0.z; a0.w += v0.w;
                a1.x += v1.x; a1.y += v1.y; a1.z += v1.z; a1.w += v1.w;
                a2.x += v2.x; a2.y += v2.y; a2.z += v2.z; a2.w += v2.w;
                a3.x += v3.x; a3.y += v3.y; a3.z += v3.z; a3.w += v3.w;
                a4.x += v4.x; a4.y += v4.y; a4.z += v4.z; a4.w += v4.w;
                a5.x += v5.x; a5.y += v5.y; a5.z += v5.z; a5.w += v5.w;
                a6.x += v6.x; a6.y += v6.y; a6.z += v6.z; a6.w += v6.w;
                a7.x += v7.x; a7.y += v7.y; a7.z += v7.z; a7.w += v7.w;
            }
            for (; j < le; j += 2) {
                int r = ord[j];
                float4 v = __ldcs(enc + (size_t)r * 64 + d4);
                a0.x += v.x; a0.y += v.y; a0.z += v.z; a0.w += v.w;
            }

            float4 r;
            r.x = ((a0.x + a1.x) + (a2.x + a3.x)) + ((a4.x + a5.x) + (a6.x + a7.x));
            r.y = ((a0.y + a1.y) + (a2.y + a3.y)) + ((a4.y + a5.y) + (a6.y + a7.y));
            r.z = ((a0.z + a1.z) + (a2.z + a3.z)) + ((a4.z + a5.z) + (a6.z + a7.z));
            r.w = ((a0.w + a1.w) + (a2.w + a3.w)) + ((a4.w + a5.w) + (a6.w + a7.w));

            float* dst = g_sum + (size_t)k * DD + (d4 << 2);
            atomicAdd(dst + 0, r.x);     // no-return -> RED.E.ADD.F32
            atomicAdd(dst + 1, r.y);
            atomicAdd(dst + 2, r.z);
            atomicAdd(dst + 3, r.w);
            __threadfence();             // make REDs visible before done-count
        }
        __syncthreads();
        if (threadIdx.x == 0) {
            int f = 0;
            if (le > la) {
                int prev = atomicAdd(&g_done[k], 1);
                f = (prev + 1 == g_expected[k]);
            }
            fin_k = f;
        }
        __syncthreads();
        if (fin_k) {
            __threadfence();             // acquire: all codes' REDs visible
            if (threadIdx.x < 64) {
                size_t o = (size_t)k * 64 + d4;
                float4 sv = __ldcg(reinterpret_cast<const float4*>(g_sum) + o);
                float4 ea = embed_avg[o];
                float inv = g_inv_smoothed[k];
                float4 nea;
                nea.x = ea.x * DECAY + ONE_MINUS_DECAY * sv.x;
                nea.y = ea.y * DECAY + ONE_MINUS_DECAY * sv.y;
                nea.z = ea.z * DECAY + ONE_MINUS_DECAY * sv.z;
                nea.w = ea.w * DECAY + ONE_MINUS_DECAY * sv.w;
                out_ea[o] = nea;
                float4 nrm;
                nrm.x = nea.x * inv; nrm.y = nea.y * inv;
                nrm.z = nea.z * inv; nrm.w = nea.w * inv;
                out_norm[o] = nrm;
                // reset scratch for next graph replay
                reinterpret_cast<float4*>(g_sum)[o] =
                    make_float4(0.f, 0.f, 0.f, 0.f);
            }
            if (threadIdx.x == 0) {
                g_done[k] = 0;
                g_kcursor[k] = 0;
            }
        }
        ++k;
        a = e2;
    }
}

// ---------------------------------------------------------------------------
// Launch
// Inputs (metadata order): indices[int32 N], encodings[f32 N*D],
//                          cluster_size[f32 K], embed_avg[f32 K*D]
// Output: concat(new_cs[K], new_ea[K*D], embed_normalized[K*D])
// ---------------------------------------------------------------------------
extern "C" void kernel_launch(void* const* d_in, const int* in_sizes, int n_in,
                              void* d_out, int out_size) {
    const int*   indices      = (const int*)d_in[0];
    const float* encodings    = (const float*)d_in[1];
    const float* cluster_size = (const float*)d_in[2];
    const float* embed_avg    = (const float*)d_in[3];

    float* out_cs   = (float*)d_out;                 // [K]
    float* out_ea   = out_cs + KK;                   // [K, D]
    float* out_norm = out_ea + (size_t)KK * DD;      // [K, D]

    k_prologue<<<NBLK, 1024>>>((const int2*)indices, cluster_size, out_cs,
                               (const float4*)embed_avg,
                               (float4*)out_ea, (float4*)out_norm);

    cudaLaunchAttribute attrs[1];
    attrs[0].id = cudaLaunchAttributeProgrammaticStreamSerialization;
    attrs[0].val.programmaticStreamSerializationAllowed = 1;

    // Reduce + fused epilogue (PDL after prologue; launches early on trigger)
    cudaLaunchConfig_t cfg = {};
    cfg.gridDim = dim3(NT, 1, 1);
    cfg.blockDim = dim3(128, 1, 1);
    cfg.dynamicSmemBytes = 0;
    cfg.stream = 0;
    cfg.attrs = attrs;
    cfg.numAttrs = 1;
    cudaLaunchKernelEx(&cfg, k_reduce, (const float4*)encodings,
                       (const float4*)embed_avg,
                       (float4*)out_ea, (float4*)out_norm);
}

// round 16
// speedup vs baseline: 1.0552x; 1.0552x over previous
#include <cuda_runtime.h>
#include <cuda_bf16.h>

// Problem constants (match reference_code)
#define NN 262144
#define KK 1024
#define DD 256
#define NBLK 128              // fused-prologue CTAs (all co-resident)
#define CHUNK 2048            // indices per CTA (NN / NBLK)
#define TILE 256              // reduce: order positions per CTA (uniform work)
#define NT (NN / TILE)        // 1024 reduce tiles
#define NPREF 448             // reduce CTAs that L2-prefetch their natural chunk
#define DECAY 0.99f
#define ONE_MINUS_DECAY 0.01f
#define EPS 1e-5f

// Scratch (device globals; no allocation allowed)
__device__ int      g_kcursor[KK];       // per-code running base (returning atomics);
                                         // after barrier = code totals. Zeroed by epilogue.
__device__ int      g_offsets[KK + 1];   // exclusive scan over codes
__device__ int      g_order[NN];         // row ids grouped by code
__device__ int      g_tilecode[NT];      // code containing order position 256*b
__device__ float    g_sum[KK * DD];      // REDG target (zeroed by epilogue/static)
__device__ float    g_inv_smoothed[KK];
__device__ unsigned g_bar_cnt[2];        // software grid barrier state
__device__ unsigned g_bar_gen[2];        // (zero-init; replay-safe: gen monotone)

// ---------------------------------------------------------------------------
// Software grid barrier (all NBLK CTAs co-resident by construction).
// ---------------------------------------------------------------------------
__device__ __forceinline__ void grid_barrier(int id) {
    __syncthreads();
    if (threadIdx.x == 0) {
        volatile unsigned* genp = &g_bar_gen[id];
        unsigned gen = *genp;
        __threadfence();
        unsigned arrived = atomicAdd(&g_bar_cnt[id], 1u);
        if (arrived == (unsigned)(NBLK - 1)) {
            g_bar_cnt[id] = 0u;
            __threadfence();
            *genp = gen + 1u;
        } else {
            while (*genp == gen) { __nanosleep(64); }
        }
        __threadfence();
    }
    __syncthreads();
}

// ---------------------------------------------------------------------------
// Fused prologue (ONE grid barrier):
//   PDL trigger fires FIRST — the reduce grid launches immediately and its
//   L2 prefetch overlaps the ENTIRE prologue (trigger placement does not
//   affect correctness: consumers still wait for full grid completion).
//   A: per-CTA smem hist; base-in-code via returning global atomicAdd.
//   barrier: g_kcursor now holds code totals.
//   C: replicated code scan -> exclusive offsets (CTA 32 writes outputs).
//   D: scatter with cursor = excl + base_in_code + local rank.
// ---------------------------------------------------------------------------
__global__ void __launch_bounds__(1024) k_prologue(
    const int2* __restrict__ idx2,
    const float* __restrict__ cluster_size,
    float* __restrict__ out_cs) {
    __shared__ int   h[KK];          // hist, then scatter cursors
    __shared__ int   sh_wsum[32];
    __shared__ float sh_wred[32];
    __shared__ float sh_n;

    // EARLIEST possible PDL trigger: reduce grid launches now; its prefetch
    // window covers the whole prologue.
    cudaTriggerProgrammaticLaunchCompletion();

    int t = threadIdx.x;
    int b = blockIdx.x;
    int lane = t & 31, warp = t >> 5;

    // ---- Phase A: per-CTA histogram (one int2 load -> registers) ----
    int base = b * CHUNK;
    int2 kk = idx2[(base >> 1) + t];     // indices base+2t, base+2t+1
    int k0 = kk.x, k1 = kk.y;
    h[t] = 0;
    __syncthreads();
    atomicAdd(&h[k0], 1);
    atomicAdd(&h[k1], 1);
    __syncthreads();
    int cnt = h[t];
    // Returning global atomic: my block's base within code t's span.
    int base_in_code = atomicAdd(&g_kcursor[t], cnt);

    grid_barrier(0);    // after this, g_kcursor[t] == total count of code t

    // ---- Phase C (replicated in every CTA): scan code totals -> excl offset ----
    int c = g_kcursor[t];
    int incl = c;
    #pragma unroll
    for (int o = 1; o < 32; o <<= 1) {
        int x = __shfl_up_sync(0xffffffffu, incl, o);
        if (lane >= o) incl += x;
    }
    if (lane == 31) sh_wsum[warp] = incl;
    __syncthreads();
    if (warp == 0) {
        int s = sh_wsum[lane];
        int si = s;
        #pragma unroll
        for (int o = 1; o < 32; o <<= 1) {
            int x = __shfl_up_sync(0xffffffffu, si, o);
            if (lane >= o) si += x;
        }
        sh_wsum[lane] = si - s;
    }
    __syncthreads();
    int excl = incl - c + sh_wsum[warp];

    if (b == 32) {
        // Outputs needed downstream (one CTA writes).
        g_offsets[t] = excl;
        if (t == KK - 1) g_offsets[KK] = excl + c;

        // Tile->code map: thread t (code t) claims every TILE-multiple in its span.
        int endp = excl + c;
        for (int m = (excl + TILE - 1) & ~(TILE - 1); m < endp; m += TILE)
            g_tilecode[m / TILE] = t;

        float ncs = cluster_size[t] * DECAY + ONE_MINUS_DECAY * (float)c;
        out_cs[t] = ncs;

        float v = ncs;
        #pragma unroll
        for (int o = 16; o > 0; o >>= 1)
            v += __shfl_down_sync(0xffffffffu, v, o);
        if (lane == 0) sh_wred[warp] = v;
        __syncthreads();
        if (warp == 0) {
            float s = sh_wred[lane];
            #pragma unroll
            for (int o = 16; o > 0; o >>= 1)
                s += __shfl_down_sync(0xffffffffu, s, o);
            if (lane == 0) sh_n = s;
        }
        __syncthreads();
        float n = sh_n;

        float smoothed = (ncs + EPS) / (n + (float)KK * EPS) * n;
        g_inv_smoothed[t] = 1.0f / smoothed;
    }

    // ---- Phase D: scatter, cursors built locally ----
    __syncthreads();                 // everyone done reading h[t] as cnt
    h[t] = excl + base_in_code;
    __syncthreads();
    int i0 = base + 2 * t;
    int p0 = atomicAdd(&h[k0], 1);
    g_order[p0] = i0;
    int p1 = atomicAdd(&h[k1], 1);
    g_order[p1] = i0 + 1;
}

// ---------------------------------------------------------------------------
// Reduce: launches early via PDL. Before the dependency sync, CTAs b<NPREF
// stream their natural 256KB chunk of encodings into L2 (prefetch.global.L2).
// Then: UNIFORM tiles over the order array, 8-deep float4 streams, flush via
// float atomicAdd (REDG, no-return) into g_sum. (R14 hot loop, untouched —
// the in-loop finisher experiment of R15 regressed and was reverted.)
// ---------------------------------------------------------------------------
__global__ void __launch_bounds__(128, 7) k_reduce(
    const float4* __restrict__ enc) {       // [N, 64] float4
    __shared__ int ord[TILE];

    int b = blockIdx.x;
    int d4 = threadIdx.x & 63;      // float4 column 0..63
    int ph = threadIdx.x >> 6;      // row phase 0..1
    int s = b * TILE;

    // ---- Overlap window: L2 prefetch of this CTA's natural chunk ----
    if (b < NPREF) {
        const char* base = reinterpret_cast<const char*>(enc) +
                           (size_t)b * TILE * (DD * 4);
        // 256 rows * 1024B = 256KB = 2048 x 128B lines; 16 per thread
        #pragma unroll
        for (int i = 0; i < 16; ++i) {
            const char* p = base + ((size_t)(i * 128 + threadIdx.x) << 7);
            asm volatile("prefetch.global.L2 [%0];" :: "l"(p));
        }
    }

    // Wait for the prologue grid (PDL; full-grid completion + visibility).
    cudaGridDependencySynchronize();

    ord[threadIdx.x]       = g_order[s + threadIdx.x];
    ord[threadIdx.x + 128] = g_order[s + threadIdx.x + 128];
    __syncthreads();

    int k = g_tilecode[b];
    int a = s;
    int send = s + TILE;

    while (a < send && k < KK) {
        int e2 = g_offsets[k + 1];
        if (e2 > send) e2 = send;
        int la = a - s;
        int le = e2 - s;

        if (le > la) {
            float4 a0 = make_float4(0.f, 0.f, 0.f, 0.f);
            float4 a1 = make_float4(0.f, 0.f, 0.f, 0.f);
            float4 a2 = make_float4(0.f, 0.f, 0.f, 0.f);
            float4 a3 = make_float4(0.f, 0.f, 0.f, 0.f);
            float4 a4 = make_float4(0.f, 0.f, 0.f, 0.f);
            float4 a5 = make_float4(0.f, 0.f, 0.f, 0.f);
            float4 a6 = make_float4(0.f, 0.f, 0.f, 0.f);
            float4 a7 = make_float4(0.f, 0.f, 0.f, 0.f);

            int j = la + ph;
            for (; j + 14 < le; j += 16) {
                int r0 = ord[j];
                int r1 = ord[j + 2];
                int r2 = ord[j + 4];
                int r3 = ord[j + 6];
                int r4 = ord[j + 8];
                int r5 = ord[j + 10];
                int r6 = ord[j + 12];
                int r7 = ord[j + 14];
                float4 v0 = __ldcs(enc + (size_t)r0 * 64 + d4);
                float4 v1 = __ldcs(enc + (size_t)r1 * 64 + d4);
                float4 v2 = __ldcs(enc + (size_t)r2 * 64 + d4);
                float4 v3 = __ldcs(enc + (size_t)r3 * 64 + d4);
                float4 v4 = __ldcs(enc + (size_t)r4 * 64 + d4);
                float4 v5 = __ldcs(enc + (size_t)r5 * 64 + d4);
                float4 v6 = __ldcs(enc + (size_t)r6 * 64 + d4);
                float4 v7 = __ldcs(enc + (size_t)r7 * 64 + d4);
                a0.x += v0.x; a0.y += v0.y; a0.z += v0.z; a0.w += v0.w;
                a1.x += v1.x; a1.y += v1.y; a1.z += v1.z; a1.w += v1.w;
                a2.x += v2.x; a2.y += v2.y; a2.z += v2.z; a2.w += v2.w;
                a3.x += v3.x; a3.y += v3.y; a3.z += v3.z; a3.w += v3.w;
                a4.x += v4.x; a4.y += v4.y; a4.z += v4.z; a4.w += v4.w;
                a5.x += v5.x; a5.y += v5.y; a5.z += v5.z; a5.w += v5.w;
                a6.x += v6.x; a6.y += v6.y; a6.z += v6.z; a6.w += v6.w;
                a7.x += v7.x; a7.y += v7.y; a7.z += v7.z; a7.w += v7.w;
            }
            for (; j < le; j += 2) {
                int r = ord[j];
                float4 v = __ldcs(enc + (size_t)r * 64 + d4);
                a0.x += v.x; a0.y += v.y; a0.z += v.z; a0.w += v.w;
            }

            float4 r;
            r.x = ((a0.x + a1.x) + (a2.x + a3.x)) + ((a4.x + a5.x) + (a6.x + a7.x));
            r.y = ((a0.y + a1.y) + (a2.y + a3.y)) + ((a4.y + a5.y) + (a6.y + a7.y));
            r.z = ((a0.z + a1.z) + (a2.z + a3.z)) + ((a4.z + a5.z) + (a6.z + a7.z));
            r.w = ((a0.w + a1.w) + (a2.w + a3.w)) + ((a4.w + a5.w) + (a6.w + a7.w));

            float* dst = g_sum + (size_t)k * DD + (d4 << 2);
            atomicAdd(dst + 0, r.x);     // no-return -> RED.E.ADD.F32
            atomicAdd(dst + 1, r.y);
            atomicAdd(dst + 2, r.z);
            atomicAdd(dst + 3, r.w);
        }
        ++k;
        a = e2;
    }
}

// ---------------------------------------------------------------------------
// Epilogue: EMA + normalize from g_sum; zero g_sum and g_kcursor for the
// next replay. PDL-chained after reduce.
// ---------------------------------------------------------------------------
__global__ void __launch_bounds__(64) k_epilogue(
    const float4* __restrict__ embed_avg,  // [K, 64] float4
    float4* __restrict__ out_ea,
    float4* __restrict__ out_norm) {
    int k = blockIdx.x;
    int d4 = threadIdx.x;           // 0..63
    size_t o = (size_t)k * 64 + d4;

    // Prologue-independent prefetch (pure input).
    float4 ea = embed_avg[o];

    cudaGridDependencySynchronize();

    float4 sv = reinterpret_cast<const float4*>(g_sum)[o];
    reinterpret_cast<float4*>(g_sum)[o] = make_float4(0.f, 0.f, 0.f, 0.f);
    if (d4 == 0) g_kcursor[k] = 0;       // reset returning-atomic bases
    float inv = g_inv_smoothed[k];

    float4 nea;
    nea.x = ea.x * DECAY + ONE_MINUS_DECAY * sv.x;
    nea.y = ea.y * DECAY + ONE_MINUS_DECAY * sv.y;
    nea.z = ea.z * DECAY + ONE_MINUS_DECAY * sv.z;
    nea.w = ea.w * DECAY + ONE_MINUS_DECAY * sv.w;
    out_ea[o] = nea;
    float4 nrm;
    nrm.x = nea.x * inv; nrm.y = nea.y * inv;
    nrm.z = nea.z * inv; nrm.w = nea.w * inv;
    out_norm[o] = nrm;
}

// ---------------------------------------------------------------------------
// Launch
// Inputs (metadata order): indices[int32 N], encodings[f32 N*D],
//                          cluster_size[f32 K], embed_avg[f32 K*D]
// Output: concat(new_cs[K], new_ea[K*D], embed_normalized[K*D])
// ---------------------------------------------------------------------------
extern "C" void kernel_launch(void* const* d_in, const int* in_sizes, int n_in,
                              void* d_out, int out_size) {
    const int*   indices      = (const int*)d_in[0];
    const float* encodings    = (const float*)d_in[1];
    const float* cluster_size = (const float*)d_in[2];
    const float* embed_avg    = (const float*)d_in[3];

    float* out_cs   = (float*)d_out;                 // [K]
    float* out_ea   = out_cs + KK;                   // [K, D]
    float* out_norm = out_ea + (size_t)KK * DD;      // [K, D]

    k_prologue<<<NBLK, 1024>>>((const int2*)indices, cluster_size, out_cs);

    cudaLaunchAttribute attrs[1];
    attrs[0].id = cudaLaunchAttributeProgrammaticStreamSerialization;
    attrs[0].val.programmaticStreamSerializationAllowed = 1;

    // Reduce (PDL after prologue; launches early on the trigger)
    cudaLaunchConfig_t cfg = {};
    cfg.gridDim = dim3(NT, 1, 1);
    cfg.blockDim = dim3(128, 1, 1);
    cfg.dynamicSmemBytes = 0;
    cfg.stream = 0;
    cfg.attrs = attrs;
    cfg.numAttrs = 1;
    cudaLaunchKernelEx(&cfg, k_reduce, (const float4*)encodings);

    // Epilogue (PDL after reduce)
    cudaLaunchConfig_t cfg2 = {};
    cfg2.gridDim = dim3(KK, 1, 1);
    cfg2.blockDim = dim3(64, 1, 1);
    cfg2.dynamicSmemBytes = 0;
    cfg2.stream = 0;
    cfg2.attrs = attrs;
    cfg2.numAttrs = 1;
    cudaLaunchKernelEx(&cfg2, k_epilogue, (const float4*)embed_avg,
                       (float4*)out_ea, (float4*)out_norm);
}